// round 4
// baseline (speedup 1.0000x reference)
#include <cuda_runtime.h>

#define D_IN  128
#define D_HID 128
#define D_OUT 64
#define MAX_N 100000
#define MAX_E 1600000

// ---------------- scratch (device globals only; no allocations) ----------------
__device__ __align__(16) float g_h1  [(size_t)MAX_N * D_HID];  // x @ W1
__device__ __align__(16) float g_agg1[(size_t)MAX_N * D_HID];  // layer-1 aggregate (+b1)
__device__ __align__(16) float g_h2  [(size_t)MAX_N * D_OUT];  // relu(agg1) @ W2
__device__ __align__(16) float g_agg2[(size_t)MAX_N * D_OUT];  // layer-2 edge aggregate
__device__ float g_deg [MAX_N];
__device__ float g_dinv[MAX_N];
__device__ int   g_src [MAX_E];
__device__ int   g_dst [MAX_E];
__device__ float g_norm[MAX_E];
__device__ int   g_is64;

// ---------------- edge dtype autodetect (single thread, deterministic) ----------------
// If the first 32 values interpreted as int64 are all valid node ids, the buffer
// really is int64. If it is int32 data, an int64 read fuses two ids -> huge value.
__global__ void k_detect(const void* __restrict__ ei, int N, int E) {
    const long long* p = (const long long*)ei;
    int n = 2 * E < 32 ? 2 * E : 32;
    int ok = 1;
    for (int i = 0; i < n; i++) {
        long long v = p[i];
        if (v < 0 || v >= N) ok = 0;
    }
    g_is64 = ok;
}

// ---------------- degree / norm precompute ----------------
__global__ void k_deg_init(int N) {
    int i = blockIdx.x * blockDim.x + threadIdx.x;
    if (i < N) g_deg[i] = 1.0f;               // self-loop
}

__global__ void k_edge_prep(const void* __restrict__ ei, int N, int E) {
    int e = blockIdx.x * blockDim.x + threadIdx.x;
    if (e >= E) return;
    int s, d;
    if (g_is64) {
        const long long* p = (const long long*)ei;
        s = (int)p[e];
        d = (int)p[(size_t)E + e];
    } else {
        const int* p = (const int*)ei;
        s = p[e];
        d = p[(size_t)E + e];
    }
    // bounds guard: never let a decode surprise become a wild atomic
    if ((unsigned)s >= (unsigned)N) s = 0;
    if ((unsigned)d >= (unsigned)N) d = 0;
    g_src[e] = s;
    g_dst[e] = d;
    atomicAdd(&g_deg[d], 1.0f);
}

__global__ void k_dinv(int N) {
    int i = blockIdx.x * blockDim.x + threadIdx.x;
    if (i < N) g_dinv[i] = rsqrtf(g_deg[i]);  // deg >= 1 always
}

__global__ void k_norm(int E) {
    int e = blockIdx.x * blockDim.x + threadIdx.x;
    if (e < E) g_norm[e] = g_dinv[g_src[e]] * g_dinv[g_dst[e]];
}

// ---------------- layer-1 init: agg1 = h1*dinv^2 + b1 ----------------
__global__ void k_init_agg1(const float* __restrict__ b1, int N) {
    const int C4 = D_HID / 4;
    int t = blockIdx.x * blockDim.x + threadIdx.x;
    if (t >= N * C4) return;
    int i = t / C4, c = t % C4;
    float w = g_dinv[i]; w = w * w;
    float4 v = ((const float4*)g_h1)[t];
    float4 b = ((const float4*)b1)[c];
    float4 o;
    o.x = fmaf(v.x, w, b.x); o.y = fmaf(v.y, w, b.y);
    o.z = fmaf(v.z, w, b.z); o.w = fmaf(v.w, w, b.w);
    ((float4*)g_agg1)[t] = o;
}

// ---------------- layer-2 scratch zero ----------------
__global__ void k_zero_agg2(int N) {
    int t = blockIdx.x * blockDim.x + threadIdx.x;
    if (t < N * (D_OUT / 4))
        ((float4*)g_agg2)[t] = make_float4(0.f, 0.f, 0.f, 0.f);
}

// ---------------- edge scatter (scalar fp atomics on device globals) ----------------
__global__ void k_scatter_l1(int E) {
    const int C4 = D_HID / 4;
    long long t = (long long)blockIdx.x * blockDim.x + threadIdx.x;
    int e = (int)(t / C4), c = (int)(t % C4);
    if (e >= E) return;
    int s = g_src[e], d = g_dst[e];
    float nrm = g_norm[e];
    float4 v = ((const float4*)g_h1)[(long long)s * C4 + c];
    float* o = g_agg1 + ((long long)d * C4 + c) * 4;
    atomicAdd(o + 0, v.x * nrm);
    atomicAdd(o + 1, v.y * nrm);
    atomicAdd(o + 2, v.z * nrm);
    atomicAdd(o + 3, v.w * nrm);
}

__global__ void k_scatter_l2(int E) {
    const int C4 = D_OUT / 4;
    long long t = (long long)blockIdx.x * blockDim.x + threadIdx.x;
    int e = (int)(t / C4), c = (int)(t % C4);
    if (e >= E) return;
    int s = g_src[e], d = g_dst[e];
    float nrm = g_norm[e];
    float4 v = ((const float4*)g_h2)[(long long)s * C4 + c];
    float* o = g_agg2 + ((long long)d * C4 + c) * 4;
    atomicAdd(o + 0, v.x * nrm);
    atomicAdd(o + 1, v.y * nrm);
    atomicAdd(o + 2, v.z * nrm);
    atomicAdd(o + 3, v.w * nrm);
}

// ---------------- final: out = h2*dinv^2 + b2 + agg2 (plain stores to d_out) ----------------
__global__ void k_final(const float* __restrict__ b2, float* __restrict__ out, int N) {
    const int C4 = D_OUT / 4;
    int t = blockIdx.x * blockDim.x + threadIdx.x;
    if (t >= N * C4) return;
    int i = t / C4, c = t % C4;
    float w = g_dinv[i]; w = w * w;
    float4 v = ((const float4*)g_h2)[t];
    float4 a = ((const float4*)g_agg2)[t];
    float4 b = ((const float4*)b2)[c];
    float4 o;
    o.x = fmaf(v.x, w, b.x) + a.x;
    o.y = fmaf(v.y, w, b.y) + a.y;
    o.z = fmaf(v.z, w, b.z) + a.z;
    o.w = fmaf(v.w, w, b.w) + a.w;
    ((float4*)out)[t] = o;
}

// ---------------- fp32 tiled GEMM body: C[M,N] = op(A[M,128]) @ B[128,N] ----------------
// BM=128, BN=64, BK=16, 256 threads, per-thread 8x4 tile.
template <bool RELU, int N>
__device__ __forceinline__ void gemm_body(const float* __restrict__ A,
                                          const float* __restrict__ B,
                                          float* __restrict__ C, int M) {
    const int BM = 128, BK = 16;
    __shared__ float As[BK][BM];   // transposed A tile
    __shared__ float Bs[BK][64];

    int block_m = blockIdx.x * BM;
    int block_n = blockIdx.y * 64;
    int tid = threadIdx.x;

    int a_row = tid >> 2;             // 0..63
    int a_col = (tid & 3) * 4;        // 0,4,8,12
    int b_row = tid >> 4;             // 0..15
    int b_col = (tid & 15) * 4;       // 0..60

    int ty = tid >> 4;                // 0..15 -> 8-row group
    int tx = tid & 15;                // 0..15 -> 4-col group

    float acc[8][4];
#pragma unroll
    for (int i = 0; i < 8; i++)
#pragma unroll
        for (int j = 0; j < 4; j++) acc[i][j] = 0.0f;

    for (int k0 = 0; k0 < 128; k0 += BK) {
#pragma unroll
        for (int p = 0; p < 2; p++) {
            int r = a_row + p * 64;
            int gm = block_m + r;
            float4 v = make_float4(0.f, 0.f, 0.f, 0.f);
            if (gm < M) v = *(const float4*)&A[(long long)gm * 128 + k0 + a_col];
            if (RELU) {
                v.x = fmaxf(v.x, 0.f); v.y = fmaxf(v.y, 0.f);
                v.z = fmaxf(v.z, 0.f); v.w = fmaxf(v.w, 0.f);
            }
            As[a_col + 0][r] = v.x;
            As[a_col + 1][r] = v.y;
            As[a_col + 2][r] = v.z;
            As[a_col + 3][r] = v.w;
        }
        *(float4*)&Bs[b_row][b_col] =
            *(const float4*)&B[(long long)(k0 + b_row) * N + block_n + b_col];
        __syncthreads();

#pragma unroll
        for (int k = 0; k < BK; k++) {
            float ra[8], rb[4];
#pragma unroll
            for (int i = 0; i < 8; i++) ra[i] = As[k][ty * 8 + i];
#pragma unroll
            for (int j = 0; j < 4; j++) rb[j] = Bs[k][tx * 4 + j];
#pragma unroll
            for (int i = 0; i < 8; i++)
#pragma unroll
                for (int j = 0; j < 4; j++) acc[i][j] = fmaf(ra[i], rb[j], acc[i][j]);
        }
        __syncthreads();
    }

#pragma unroll
    for (int i = 0; i < 8; i++) {
        int gm = block_m + ty * 8 + i;
        if (gm < M)
            *(float4*)&C[(long long)gm * N + block_n + tx * 4] =
                make_float4(acc[i][0], acc[i][1], acc[i][2], acc[i][3]);
    }
}

__global__ void k_gemm_l1(const float* __restrict__ x, const float* __restrict__ W1, int M) {
    gemm_body<false, D_HID>(x, W1, g_h1, M);
}
__global__ void k_gemm_l2(const float* __restrict__ W2, int M) {
    gemm_body<true, D_OUT>(g_agg1, W2, g_h2, M);
}

// ---------------- launch (kernel launches ONLY — no runtime API calls) ----------------
extern "C" void kernel_launch(void* const* d_in, const int* in_sizes, int n_in,
                              void* d_out, int out_size) {
    const float* x  = (const float*)d_in[0];
    const void*  ei = d_in[1];
    // d_in[2] = batch (unused)
    const float* W1 = (const float*)d_in[3];
    const float* b1 = (const float*)d_in[4];
    const float* W2 = (const float*)d_in[5];
    const float* b2 = (const float*)d_in[6];
    float* out = (float*)d_out;

    int N = in_sizes[0] / D_IN;
    int E = in_sizes[1] / 2;

    const int T = 256;

    // edge dtype detect + degree / norm
    k_detect<<<1, 1>>>(ei, N, E);
    k_deg_init<<<(N + T - 1) / T, T>>>(N);
    k_edge_prep<<<(E + T - 1) / T, T>>>(ei, N, E);
    k_dinv<<<(N + T - 1) / T, T>>>(N);
    k_norm<<<(E + T - 1) / T, T>>>(E);

    // layer 1
    {
        dim3 grid((N + 127) / 128, D_HID / 64);
        k_gemm_l1<<<grid, 256>>>(x, W1, N);
        int total = N * (D_HID / 4);
        k_init_agg1<<<(total + T - 1) / T, T>>>(b1, N);
        long long st = (long long)E * (D_HID / 4);
        k_scatter_l1<<<(unsigned)((st + T - 1) / T), T>>>(E);
    }

    // layer 2
    {
        dim3 grid((N + 127) / 128, D_OUT / 64);
        k_gemm_l2<<<grid, 256>>>(W2, N);
        int ztotal = N * (D_OUT / 4);
        k_zero_agg2<<<(ztotal + T - 1) / T, T>>>(N);
        long long st = (long long)E * (D_OUT / 4);
        k_scatter_l2<<<(unsigned)((st + T - 1) / T), T>>>(E);
        k_final<<<(ztotal + T - 1) / T, T>>>(b2, out, N);
    }
}

// round 5
// speedup vs baseline: 1.0025x; 1.0025x over previous
#include <cuda_runtime.h>

#define D_IN  128
#define D_HID 128
#define D_OUT 64
#define MAX_N 100000
#define MAX_E 1600000

// ---------------- scratch (device globals only; no allocations) ----------------
__device__ __align__(16) float g_h1  [(size_t)MAX_N * D_HID];  // x @ W1
__device__ __align__(16) float g_agg1[(size_t)MAX_N * D_HID];  // layer-1 aggregate (+b1)
__device__ __align__(16) float g_h2  [(size_t)MAX_N * D_OUT];  // relu(agg1) @ W2
__device__ __align__(16) float g_agg2[(size_t)MAX_N * D_OUT];  // layer-2 edge aggregate
__device__ float g_deg [MAX_N];
__device__ float g_dinv[MAX_N];
__device__ int   g_src [MAX_E];
__device__ int   g_dst [MAX_E];
__device__ float g_norm[MAX_E];
__device__ int   g_is64;

// ---------------- edge dtype autodetect (single thread, deterministic) ----------------
// If the first 32 values interpreted as int64 are all valid node ids, the buffer
// really is int64. If it is int32 data, an int64 read fuses two ids -> huge value.
__global__ void k_detect(const void* __restrict__ ei, int N, int E) {
    const long long* p = (const long long*)ei;
    int n = 2 * E < 32 ? 2 * E : 32;
    int ok = 1;
    for (int i = 0; i < n; i++) {
        long long v = p[i];
        if (v < 0 || v >= N) ok = 0;
    }
    g_is64 = ok;
}

// ---------------- degree / norm precompute ----------------
__global__ void k_deg_init(int N) {
    int i = blockIdx.x * blockDim.x + threadIdx.x;
    if (i < N) g_deg[i] = 1.0f;               // self-loop
}

__global__ void k_edge_prep(const void* __restrict__ ei, int N, int E) {
    int e = blockIdx.x * blockDim.x + threadIdx.x;
    if (e >= E) return;
    int s, d;
    if (g_is64) {
        const long long* p = (const long long*)ei;
        s = (int)p[e];
        d = (int)p[(size_t)E + e];
    } else {
        const int* p = (const int*)ei;
        s = p[e];
        d = p[(size_t)E + e];
    }
    // bounds guard: never let a decode surprise become a wild atomic
    if ((unsigned)s >= (unsigned)N) s = 0;
    if ((unsigned)d >= (unsigned)N) d = 0;
    g_src[e] = s;
    g_dst[e] = d;
    atomicAdd(&g_deg[d], 1.0f);
}

__global__ void k_dinv(int N) {
    int i = blockIdx.x * blockDim.x + threadIdx.x;
    if (i < N) g_dinv[i] = rsqrtf(g_deg[i]);  // deg >= 1 always
}

__global__ void k_norm(int E) {
    int e = blockIdx.x * blockDim.x + threadIdx.x;
    if (e < E) g_norm[e] = g_dinv[g_src[e]] * g_dinv[g_dst[e]];
}

// ---------------- layer-1 init: agg1 = h1*dinv^2 + b1 ----------------
__global__ void k_init_agg1(const float* __restrict__ b1, int N) {
    const int C4 = D_HID / 4;
    int t = blockIdx.x * blockDim.x + threadIdx.x;
    if (t >= N * C4) return;
    int i = t / C4, c = t % C4;
    float w = g_dinv[i]; w = w * w;
    float4 v = ((const float4*)g_h1)[t];
    float4 b = ((const float4*)b1)[c];
    float4 o;
    o.x = fmaf(v.x, w, b.x); o.y = fmaf(v.y, w, b.y);
    o.z = fmaf(v.z, w, b.z); o.w = fmaf(v.w, w, b.w);
    ((float4*)g_agg1)[t] = o;
}

// ---------------- layer-2 scratch zero ----------------
__global__ void k_zero_agg2(int N) {
    int t = blockIdx.x * blockDim.x + threadIdx.x;
    if (t < N * (D_OUT / 4))
        ((float4*)g_agg2)[t] = make_float4(0.f, 0.f, 0.f, 0.f);
}

// ---------------- edge scatter (scalar fp atomics on device globals) ----------------
__global__ void k_scatter_l1(int E) {
    const int C4 = D_HID / 4;
    long long t = (long long)blockIdx.x * blockDim.x + threadIdx.x;
    int e = (int)(t / C4), c = (int)(t % C4);
    if (e >= E) return;
    int s = g_src[e], d = g_dst[e];
    float nrm = g_norm[e];
    float4 v = ((const float4*)g_h1)[(long long)s * C4 + c];
    float* o = g_agg1 + ((long long)d * C4 + c) * 4;
    atomicAdd(o + 0, v.x * nrm);
    atomicAdd(o + 1, v.y * nrm);
    atomicAdd(o + 2, v.z * nrm);
    atomicAdd(o + 3, v.w * nrm);
}

__global__ void k_scatter_l2(int E) {
    const int C4 = D_OUT / 4;
    long long t = (long long)blockIdx.x * blockDim.x + threadIdx.x;
    int e = (int)(t / C4), c = (int)(t % C4);
    if (e >= E) return;
    int s = g_src[e], d = g_dst[e];
    float nrm = g_norm[e];
    float4 v = ((const float4*)g_h2)[(long long)s * C4 + c];
    float* o = g_agg2 + ((long long)d * C4 + c) * 4;
    atomicAdd(o + 0, v.x * nrm);
    atomicAdd(o + 1, v.y * nrm);
    atomicAdd(o + 2, v.z * nrm);
    atomicAdd(o + 3, v.w * nrm);
}

// ---------------- final: out = h2*dinv^2 + b2 + agg2 (plain stores to d_out) ----------------
__global__ void k_final(const float* __restrict__ b2, float* __restrict__ out, int N) {
    const int C4 = D_OUT / 4;
    int t = blockIdx.x * blockDim.x + threadIdx.x;
    if (t >= N * C4) return;
    int i = t / C4, c = t % C4;
    float w = g_dinv[i]; w = w * w;
    float4 v = ((const float4*)g_h2)[t];
    float4 a = ((const float4*)g_agg2)[t];
    float4 b = ((const float4*)b2)[c];
    float4 o;
    o.x = fmaf(v.x, w, b.x) + a.x;
    o.y = fmaf(v.y, w, b.y) + a.y;
    o.z = fmaf(v.z, w, b.z) + a.z;
    o.w = fmaf(v.w, w, b.w) + a.w;
    ((float4*)out)[t] = o;
}

// ---------------- fp32 tiled GEMM body: C[M,N] = op(A[M,128]) @ B[128,N] ----------------
// BM=128, BN=64, BK=16, 256 threads, per-thread 8x4 tile.
template <bool RELU, int N>
__device__ __forceinline__ void gemm_body(const float* __restrict__ A,
                                          const float* __restrict__ B,
                                          float* __restrict__ C, int M) {
    const int BM = 128, BK = 16;
    __shared__ float As[BK][BM];   // transposed A tile
    __shared__ float Bs[BK][64];

    int block_m = blockIdx.x * BM;
    int block_n = blockIdx.y * 64;
    int tid = threadIdx.x;

    int a_row = tid >> 2;             // 0..63
    int a_col = (tid & 3) * 4;        // 0,4,8,12
    int b_row = tid >> 4;             // 0..15
    int b_col = (tid & 15) * 4;       // 0..60

    int ty = tid >> 4;                // 0..15 -> 8-row group
    int tx = tid & 15;                // 0..15 -> 4-col group

    float acc[8][4];
#pragma unroll
    for (int i = 0; i < 8; i++)
#pragma unroll
        for (int j = 0; j < 4; j++) acc[i][j] = 0.0f;

    for (int k0 = 0; k0 < 128; k0 += BK) {
#pragma unroll
        for (int p = 0; p < 2; p++) {
            int r = a_row + p * 64;
            int gm = block_m + r;
            float4 v = make_float4(0.f, 0.f, 0.f, 0.f);
            if (gm < M) v = *(const float4*)&A[(long long)gm * 128 + k0 + a_col];
            if (RELU) {
                v.x = fmaxf(v.x, 0.f); v.y = fmaxf(v.y, 0.f);
                v.z = fmaxf(v.z, 0.f); v.w = fmaxf(v.w, 0.f);
            }
            As[a_col + 0][r] = v.x;
            As[a_col + 1][r] = v.y;
            As[a_col + 2][r] = v.z;
            As[a_col + 3][r] = v.w;
        }
        *(float4*)&Bs[b_row][b_col] =
            *(const float4*)&B[(long long)(k0 + b_row) * N + block_n + b_col];
        __syncthreads();

#pragma unroll
        for (int k = 0; k < BK; k++) {
            float ra[8], rb[4];
#pragma unroll
            for (int i = 0; i < 8; i++) ra[i] = As[k][ty * 8 + i];
#pragma unroll
            for (int j = 0; j < 4; j++) rb[j] = Bs[k][tx * 4 + j];
#pragma unroll
            for (int i = 0; i < 8; i++)
#pragma unroll
                for (int j = 0; j < 4; j++) acc[i][j] = fmaf(ra[i], rb[j], acc[i][j]);
        }
        __syncthreads();
    }

#pragma unroll
    for (int i = 0; i < 8; i++) {
        int gm = block_m + ty * 8 + i;
        if (gm < M)
            *(float4*)&C[(long long)gm * N + block_n + tx * 4] =
                make_float4(acc[i][0], acc[i][1], acc[i][2], acc[i][3]);
    }
}

__global__ void k_gemm_l1(const float* __restrict__ x, const float* __restrict__ W1, int M) {
    gemm_body<false, D_HID>(x, W1, g_h1, M);
}
__global__ void k_gemm_l2(const float* __restrict__ W2, int M) {
    gemm_body<true, D_OUT>(g_agg1, W2, g_h2, M);
}

// ---------------- launch (kernel launches ONLY — no runtime API calls) ----------------
extern "C" void kernel_launch(void* const* d_in, const int* in_sizes, int n_in,
                              void* d_out, int out_size) {
    const float* x  = (const float*)d_in[0];
    const void*  ei = d_in[1];
    // d_in[2] = batch (unused)
    const float* W1 = (const float*)d_in[3];
    const float* b1 = (const float*)d_in[4];
    const float* W2 = (const float*)d_in[5];
    const float* b2 = (const float*)d_in[6];
    float* out = (float*)d_out;

    int N = in_sizes[0] / D_IN;
    int E = in_sizes[1] / 2;

    const int T = 256;

    // edge dtype detect + degree / norm
    k_detect<<<1, 1>>>(ei, N, E);
    k_deg_init<<<(N + T - 1) / T, T>>>(N);
    k_edge_prep<<<(E + T - 1) / T, T>>>(ei, N, E);
    k_dinv<<<(N + T - 1) / T, T>>>(N);
    k_norm<<<(E + T - 1) / T, T>>>(E);

    // layer 1
    {
        dim3 grid((N + 127) / 128, D_HID / 64);
        k_gemm_l1<<<grid, 256>>>(x, W1, N);
        int total = N * (D_HID / 4);
        k_init_agg1<<<(total + T - 1) / T, T>>>(b1, N);
        long long st = (long long)E * (D_HID / 4);
        k_scatter_l1<<<(unsigned)((st + T - 1) / T), T>>>(E);
    }

    // layer 2
    {
        dim3 grid((N + 127) / 128, D_OUT / 64);
        k_gemm_l2<<<grid, 256>>>(W2, N);
        int ztotal = N * (D_OUT / 4);
        k_zero_agg2<<<(ztotal + T - 1) / T, T>>>(N);
        long long st = (long long)E * (D_OUT / 4);
        k_scatter_l2<<<(unsigned)((st + T - 1) / T), T>>>(E);
        k_final<<<(ztotal + T - 1) / T, T>>>(b2, out, N);
    }
}

// round 6
// speedup vs baseline: 2.7094x; 2.7026x over previous
#include <cuda_runtime.h>

#define D_IN  128
#define D_HID 128
#define D_OUT 64
#define MAX_N 100000
#define MAX_E 1600000
#define SCAN_B 1024

// ---------------- scratch (device globals only; no allocations) ----------------
__device__ __align__(16) float g_h1  [(size_t)MAX_N * D_HID];  // x @ W1
__device__ __align__(16) float g_agg1[(size_t)MAX_N * D_HID];  // layer-1 aggregate (+b1)
__device__ __align__(16) float g_h2  [(size_t)MAX_N * D_OUT];  // relu(agg1) @ W2
__device__ float g_dinv[MAX_N];
__device__ int   g_cnt [MAX_N];        // in-degree (excl. self-loop)
__device__ int   g_cur [MAX_N];        // fill cursor
__device__ int   g_off [MAX_N];        // CSR row offsets (exclusive scan of cnt)
__device__ int   g_bsum[SCAN_B];       // scan block sums
__device__ int   g_src [MAX_E];
__device__ int   g_dst [MAX_E];
__device__ int   g_csr_src [MAX_E];    // edges sorted by dst
__device__ float g_csr_norm[MAX_E];
__device__ int   g_is64;

// ---------------- edge dtype autodetect ----------------
__global__ void k_detect(const void* __restrict__ ei, int N, int E) {
    const long long* p = (const long long*)ei;
    int n = 2 * E < 32 ? 2 * E : 32;
    int ok = 1;
    for (int i = 0; i < n; i++) {
        long long v = p[i];
        if (v < 0 || v >= N) ok = 0;
    }
    g_is64 = ok;
}

// ---------------- zero counters ----------------
__global__ void k_zero_cnt(int N) {
    int i = blockIdx.x * blockDim.x + threadIdx.x;
    if (i < N) { g_cnt[i] = 0; g_cur[i] = 0; }
}

// ---------------- decode edges + count in-degree ----------------
__global__ void k_edge_prep(const void* __restrict__ ei, int N, int E) {
    int e = blockIdx.x * blockDim.x + threadIdx.x;
    if (e >= E) return;
    int s, d;
    if (g_is64) {
        const long long* p = (const long long*)ei;
        s = (int)p[e];
        d = (int)p[(size_t)E + e];
    } else {
        const int* p = (const int*)ei;
        s = p[e];
        d = p[(size_t)E + e];
    }
    if ((unsigned)s >= (unsigned)N) s = 0;
    if ((unsigned)d >= (unsigned)N) d = 0;
    g_src[e] = s;
    g_dst[e] = d;
    atomicAdd(&g_cnt[d], 1);
}

__global__ void k_dinv(int N) {
    int i = blockIdx.x * blockDim.x + threadIdx.x;
    if (i < N) g_dinv[i] = rsqrtf((float)(g_cnt[i] + 1));   // +1 self-loop
}

// ---------------- 3-kernel exclusive scan of g_cnt -> g_off ----------------
__global__ void k_scan1(int N) {
    __shared__ int sh[SCAN_B];
    int i = blockIdx.x * SCAN_B + threadIdx.x;
    int v = (i < N) ? g_cnt[i] : 0;
    sh[threadIdx.x] = v;
    __syncthreads();
    for (int o = 1; o < SCAN_B; o <<= 1) {
        int t = (threadIdx.x >= o) ? sh[threadIdx.x - o] : 0;
        __syncthreads();
        sh[threadIdx.x] += t;
        __syncthreads();
    }
    if (i < N) g_off[i] = sh[threadIdx.x] - v;               // exclusive
    if (threadIdx.x == SCAN_B - 1) g_bsum[blockIdx.x] = sh[SCAN_B - 1];
}

__global__ void k_scan2(int nb) {
    __shared__ int sh[SCAN_B];
    int v = (threadIdx.x < nb) ? g_bsum[threadIdx.x] : 0;
    sh[threadIdx.x] = v;
    __syncthreads();
    for (int o = 1; o < SCAN_B; o <<= 1) {
        int t = (threadIdx.x >= o) ? sh[threadIdx.x - o] : 0;
        __syncthreads();
        sh[threadIdx.x] += t;
        __syncthreads();
    }
    if (threadIdx.x < nb) g_bsum[threadIdx.x] = sh[threadIdx.x] - v;  // exclusive
}

__global__ void k_scan3(int N) {
    int i = blockIdx.x * SCAN_B + threadIdx.x;
    if (i < N) g_off[i] += g_bsum[blockIdx.x];
}

// ---------------- fill CSR (sorted by dst) with norm ----------------
__global__ void k_fill(int E) {
    int e = blockIdx.x * blockDim.x + threadIdx.x;
    if (e >= E) return;
    int s = g_src[e], d = g_dst[e];
    int pos = g_off[d] + atomicAdd(&g_cur[d], 1);
    g_csr_src[pos]  = s;
    g_csr_norm[pos] = g_dinv[s] * g_dinv[d];
}

// ---------------- layer-1 gather: warp per node, float4 lanes (128 cols) ----------------
__global__ void k_gather_l1(const float* __restrict__ b1, int N) {
    int gw   = (blockIdx.x * blockDim.x + threadIdx.x) >> 5;
    int lane = threadIdx.x & 31;
    if (gw >= N) return;
    const float4* h = (const float4*)g_h1;
    float w = g_dinv[gw]; w = w * w;
    float4 v  = h[(long long)gw * 32 + lane];
    float4 b  = ((const float4*)b1)[lane];
    float4 acc;
    acc.x = fmaf(v.x, w, b.x); acc.y = fmaf(v.y, w, b.y);
    acc.z = fmaf(v.z, w, b.z); acc.w = fmaf(v.w, w, b.w);
    int beg = g_off[gw], end = beg + g_cnt[gw];
#pragma unroll 4
    for (int j = beg; j < end; j++) {
        int   s   = g_csr_src[j];
        float nrm = g_csr_norm[j];
        float4 u = h[(long long)s * 32 + lane];
        acc.x = fmaf(u.x, nrm, acc.x);
        acc.y = fmaf(u.y, nrm, acc.y);
        acc.z = fmaf(u.z, nrm, acc.z);
        acc.w = fmaf(u.w, nrm, acc.w);
    }
    ((float4*)g_agg1)[(long long)gw * 32 + lane] = acc;
}

// ---------------- layer-2 gather: warp per node, float2 lanes (64 cols), writes d_out ----------------
__global__ void k_gather_l2(const float* __restrict__ b2, float* __restrict__ out, int N) {
    int gw   = (blockIdx.x * blockDim.x + threadIdx.x) >> 5;
    int lane = threadIdx.x & 31;
    if (gw >= N) return;
    const float2* h = (const float2*)g_h2;
    float w = g_dinv[gw]; w = w * w;
    float2 v = h[(long long)gw * 32 + lane];
    float2 b = ((const float2*)b2)[lane];
    float2 acc;
    acc.x = fmaf(v.x, w, b.x);
    acc.y = fmaf(v.y, w, b.y);
    int beg = g_off[gw], end = beg + g_cnt[gw];
#pragma unroll 4
    for (int j = beg; j < end; j++) {
        int   s   = g_csr_src[j];
        float nrm = g_csr_norm[j];
        float2 u = h[(long long)s * 32 + lane];
        acc.x = fmaf(u.x, nrm, acc.x);
        acc.y = fmaf(u.y, nrm, acc.y);
    }
    ((float2*)out)[(long long)gw * 32 + lane] = acc;
}

// ---------------- fp32 tiled GEMM body: C[M,N] = op(A[M,128]) @ B[128,N] ----------------
template <bool RELU, int N>
__device__ __forceinline__ void gemm_body(const float* __restrict__ A,
                                          const float* __restrict__ B,
                                          float* __restrict__ C, int M) {
    const int BM = 128, BK = 16;
    __shared__ float As[BK][BM];   // transposed A tile
    __shared__ float Bs[BK][64];

    int block_m = blockIdx.x * BM;
    int block_n = blockIdx.y * 64;
    int tid = threadIdx.x;

    int a_row = tid >> 2;
    int a_col = (tid & 3) * 4;
    int b_row = tid >> 4;
    int b_col = (tid & 15) * 4;

    int ty = tid >> 4;
    int tx = tid & 15;

    float acc[8][4];
#pragma unroll
    for (int i = 0; i < 8; i++)
#pragma unroll
        for (int j = 0; j < 4; j++) acc[i][j] = 0.0f;

    for (int k0 = 0; k0 < 128; k0 += BK) {
#pragma unroll
        for (int p = 0; p < 2; p++) {
            int r = a_row + p * 64;
            int gm = block_m + r;
            float4 v = make_float4(0.f, 0.f, 0.f, 0.f);
            if (gm < M) v = *(const float4*)&A[(long long)gm * 128 + k0 + a_col];
            if (RELU) {
                v.x = fmaxf(v.x, 0.f); v.y = fmaxf(v.y, 0.f);
                v.z = fmaxf(v.z, 0.f); v.w = fmaxf(v.w, 0.f);
            }
            As[a_col + 0][r] = v.x;
            As[a_col + 1][r] = v.y;
            As[a_col + 2][r] = v.z;
            As[a_col + 3][r] = v.w;
        }
        *(float4*)&Bs[b_row][b_col] =
            *(const float4*)&B[(long long)(k0 + b_row) * N + block_n + b_col];
        __syncthreads();

#pragma unroll
        for (int k = 0; k < BK; k++) {
            float ra[8], rb[4];
#pragma unroll
            for (int i = 0; i < 8; i++) ra[i] = As[k][ty * 8 + i];
#pragma unroll
            for (int j = 0; j < 4; j++) rb[j] = Bs[k][tx * 4 + j];
#pragma unroll
            for (int i = 0; i < 8; i++)
#pragma unroll
                for (int j = 0; j < 4; j++) acc[i][j] = fmaf(ra[i], rb[j], acc[i][j]);
        }
        __syncthreads();
    }

#pragma unroll
    for (int i = 0; i < 8; i++) {
        int gm = block_m + ty * 8 + i;
        if (gm < M)
            *(float4*)&C[(long long)gm * N + block_n + tx * 4] =
                make_float4(acc[i][0], acc[i][1], acc[i][2], acc[i][3]);
    }
}

__global__ void k_gemm_l1(const float* __restrict__ x, const float* __restrict__ W1, int M) {
    gemm_body<false, D_HID>(x, W1, g_h1, M);
}
__global__ void k_gemm_l2(const float* __restrict__ W2, int M) {
    gemm_body<true, D_OUT>(g_agg1, W2, g_h2, M);
}

// ---------------- launch (kernel launches ONLY) ----------------
extern "C" void kernel_launch(void* const* d_in, const int* in_sizes, int n_in,
                              void* d_out, int out_size) {
    const float* x  = (const float*)d_in[0];
    const void*  ei = d_in[1];
    // d_in[2] = batch (unused)
    const float* W1 = (const float*)d_in[3];
    const float* b1 = (const float*)d_in[4];
    const float* W2 = (const float*)d_in[5];
    const float* b2 = (const float*)d_in[6];
    float* out = (float*)d_out;

    int N = in_sizes[0] / D_IN;
    int E = in_sizes[1] / 2;

    const int T = 256;
    int nb = (N + SCAN_B - 1) / SCAN_B;

    // ---- CSR build ----
    k_detect<<<1, 1>>>(ei, N, E);
    k_zero_cnt<<<(N + T - 1) / T, T>>>(N);
    k_edge_prep<<<(E + T - 1) / T, T>>>(ei, N, E);
    k_dinv<<<(N + T - 1) / T, T>>>(N);
    k_scan1<<<nb, SCAN_B>>>(N);
    k_scan2<<<1, SCAN_B>>>(nb);
    k_scan3<<<nb, SCAN_B>>>(N);
    k_fill<<<(E + T - 1) / T, T>>>(E);

    // ---- layer 1: h1 = x @ W1 ; agg1 = D^-1/2 (A+I) D^-1/2 h1 + b1 ----
    {
        dim3 grid((N + 127) / 128, D_HID / 64);
        k_gemm_l1<<<grid, 256>>>(x, W1, N);
        int blocks = (N * 32 + T - 1) / T;           // warp per node
        k_gather_l1<<<blocks, T>>>(b1, N);
    }

    // ---- layer 2: h2 = relu(agg1) @ W2 ; out = D^-1/2 (A+I) D^-1/2 h2 + b2 ----
    {
        dim3 grid((N + 127) / 128, D_OUT / 64);
        k_gemm_l2<<<grid, 256>>>(W2, N);
        int blocks = (N * 32 + T - 1) / T;
        k_gather_l2<<<blocks, T>>>(b2, out, N);
    }
}